// round 10
// baseline (speedup 1.0000x reference)
#include <cuda_runtime.h>
#include <cuda_fp16.h>
#include <math.h>
#include <stdint.h>

#define B_ 4
#define S_ 4096
#define BS_ (B_*S_)      // 16384 tokens
#define D_ 1024
#define Q_ 1024
#define CH 64            // scan chunk length
#define NC (S_/CH)       // 64 chunks per batch

// ---------------- scratch (static device globals; no cudaMalloc allowed) ----
__device__ __align__(128) float g_V[BS_*Q_];        // 64 MB: V = emb@Wv + bv
__device__ __align__(128) float g_part[B_*NC*Q_];   // 1 MB: chunk partial sums
__device__ float g_s[BS_];
__device__ float g_e[BS_];                          // exp(s)
__device__ float g_coef[BS_];                       // exp(-prefix_max)
__device__ float g_wkq[D_];                         // Wk @ query^T
__device__ float g_skq;                             // bk . query
__device__ __align__(128) __half g_wt_h[Q_*D_];     // Wv^T fp16 [n][k]
__device__ __align__(128) __half g_a_h[BS_*D_];     // gathered emb fp16 [m][k]

// ---------------- helpers ----------------------------------------------------
__device__ __forceinline__ uint32_t smem_u32(const void* p) {
    uint32_t a;
    asm("{ .reg .u64 t; cvta.to.shared.u64 t, %1; cvt.u32.u64 %0, t; }"
        : "=r"(a) : "l"(p));
    return a;
}
static __device__ __forceinline__ uint32_t pack_h2(float x, float y) {
    __half2 h = __floats2half2_rn(x, y);
    return *(uint32_t*)&h;
}
#define LDSM_X4(r0, r1, r2, r3, addr) \
    asm volatile("ldmatrix.sync.aligned.m8n8.x4.shared.b16 {%0,%1,%2,%3}, [%4];" \
                 : "=r"(r0), "=r"(r1), "=r"(r2), "=r"(r3) : "r"(addr))
#define MMA_F16(d, a0, a1, a2, a3, b0, b1) \
    asm volatile("mma.sync.aligned.m16n8k16.row.col.f32.f16.f16.f32 " \
                 "{%0,%1,%2,%3}, {%4,%5,%6,%7}, {%8,%9}, {%0,%1,%2,%3};" \
                 : "+f"((d)[0]), "+f"((d)[1]), "+f"((d)[2]), "+f"((d)[3]) \
                 : "r"(a0), "r"(a1), "r"(a2), "r"(a3), "r"(b0), "r"(b1))
#define CP16(dst, src) \
    asm volatile("cp.async.cg.shared.global [%0], [%1], 16;" \
                 :: "r"(dst), "l"(src) : "memory")
#define CP_COMMIT() asm volatile("cp.async.commit_group;" ::: "memory")
#define CP_WAIT(n)  asm volatile("cp.async.wait_group %0;" :: "n"(n) : "memory")

// ---------------- kernel 1: wkq[d] = Wk[d,:] . query ;  skq = bk . query ----
__global__ void k_wkq(const float* __restrict__ Wk, const float* __restrict__ bk,
                      const float* __restrict__ query) {
    __shared__ float red[256];
    int d = blockIdx.x;
    const float* row = (d < D_) ? (Wk + (size_t)d * Q_) : bk;
    float acc = 0.f;
    for (int q = threadIdx.x; q < Q_; q += 256) acc += row[q] * query[q];
    red[threadIdx.x] = acc;
    __syncthreads();
    for (int s = 128; s > 0; s >>= 1) {
        if (threadIdx.x < s) red[threadIdx.x] += red[threadIdx.x + s];
        __syncthreads();
    }
    if (threadIdx.x == 0) {
        if (d < D_) g_wkq[d] = red[0]; else g_skq = red[0];
    }
}

// ---------------- kernel 2: fused gather+fp16 convert+score ------------------
// block = 256 threads = 2 rows (128 threads/row, 8 floats each)
__global__ void k_ascore(const float* __restrict__ emb, const int* __restrict__ ids) {
    __shared__ float swkq[D_];
    __shared__ float red[8];
    int tid = threadIdx.x;
    for (int i = tid; i < D_; i += 256) swkq[i] = g_wkq[i];
    __syncthreads();
    int m = blockIdx.x * 2 + (tid >> 7);
    int col = (tid & 127) * 8;
    const float* src = emb + (size_t)ids[m] * D_ + col;
    float4 x = ((const float4*)src)[0];
    float4 y = ((const float4*)src)[1];
    uint4 hv = make_uint4(pack_h2(x.x, x.y), pack_h2(x.z, x.w),
                          pack_h2(y.x, y.y), pack_h2(y.z, y.w));
    *(uint4*)(g_a_h + (size_t)m * D_ + col) = hv;
    float acc = x.x * swkq[col]     + x.y * swkq[col + 1]
              + x.z * swkq[col + 2] + x.w * swkq[col + 3]
              + y.x * swkq[col + 4] + y.y * swkq[col + 5]
              + y.z * swkq[col + 6] + y.w * swkq[col + 7];
    #pragma unroll
    for (int o = 16; o > 0; o >>= 1) acc += __shfl_xor_sync(0xffffffffu, acc, o);
    int warp = tid >> 5;
    if ((tid & 31) == 0) red[warp] = acc;
    __syncthreads();
    if ((tid & 127) == 0) {
        int base = (tid >> 7) * 4;
        g_s[m] = red[base] + red[base + 1] + red[base + 2] + red[base + 3] + g_skq;
    }
}

// ---------------- kernel 2b: transpose + convert Wv -> Wt fp16 [n][k] --------
__global__ void k_wt(const float* __restrict__ Wv) {
    __shared__ float tile[32][33];
    int kb = blockIdx.y * 32, nb = blockIdx.x * 32;
    int tx = threadIdx.x, ty = threadIdx.y;          // 32 x 8
    #pragma unroll
    for (int j = 0; j < 32; j += 8)
        tile[ty + j][tx] = Wv[(size_t)(kb + ty + j) * Q_ + nb + tx];
    __syncthreads();
    #pragma unroll
    for (int j = 0; j < 32; j += 8) {
        float v = tile[tx][ty + j];                   // = Wv[kb+tx][nb+ty+j]
        g_wt_h[(size_t)(nb + ty + j) * D_ + kb + tx] = __float2half_rn(v);
    }
}

// ---------------- kernel 3: fp16 single-MMA GEMM with cp.async pipeline ------
// CTA 128x128, BK=64, 3 stages. 8 warps each 32(M)x64(N). Padded stride 72.
#define BKK 64
#define SST 72
#define STG 3
#define MATB (128 * SST * 2)              // bytes per matrix per stage (18432)
#define STGB (2 * MATB)                   // bytes per stage (36864)
#define NCHK (D_ / BKK)                   // 16 K-chunks

__global__ __launch_bounds__(256, 2) void k_gemm_mma(const float* __restrict__ bv) {
    extern __shared__ __align__(16) char smraw[];
    uint32_t sbase = smem_u32(smraw);
    int tid = threadIdx.x, lane = tid & 31, wid = tid >> 5;
    int wm = wid & 3, wn = wid >> 2;
    int bm = blockIdx.y * 128, bn = blockIdx.x * 128;
    int lrow = tid >> 1, lhalf = (tid & 1) * 32;     // loader: row, 32-k half

    const __half* srcA = g_a_h + (size_t)(bm + lrow) * D_ + lhalf;
    const __half* srcB = g_wt_h + (size_t)(bn + lrow) * D_ + lhalf;
    uint32_t dsto = (uint32_t)(lrow * SST + lhalf) * 2;  // byte offset in matrix

    uint32_t aoff = (uint32_t)((wm * 32 + (lane & 15)) * SST + (lane >> 4) * 8) * 2;
    uint32_t boff = (uint32_t)((wn * 64 + (lane & 15)) * SST + (lane >> 4) * 8) * 2;

    float acc[2][8][4];
    #pragma unroll
    for (int f = 0; f < 2; f++)
        #pragma unroll
        for (int g = 0; g < 8; g++)
            #pragma unroll
            for (int v = 0; v < 4; v++) acc[f][g][v] = 0.f;

    // prologue: fill STG-1 stages
    #pragma unroll
    for (int s = 0; s < STG - 1; s++) {
        uint32_t sb = sbase + s * STGB + dsto;
        int k0 = s * BKK;
        CP16(sb,             srcA + k0);
        CP16(sb + 16,        srcA + k0 + 8);
        CP16(sb + 32,        srcA + k0 + 16);
        CP16(sb + 48,        srcA + k0 + 24);
        CP16(sb + MATB,      srcB + k0);
        CP16(sb + MATB + 16, srcB + k0 + 8);
        CP16(sb + MATB + 32, srcB + k0 + 16);
        CP16(sb + MATB + 48, srcB + k0 + 24);
        CP_COMMIT();
    }

    for (int ch = 0; ch < NCHK; ch++) {
        CP_WAIT(STG - 2);
        __syncthreads();
        // issue loads for chunk ch+STG-1 (overlap with compute below)
        {
            int nc = ch + STG - 1;
            if (nc < NCHK) {
                uint32_t sb = sbase + (nc % STG) * STGB + dsto;
                int k0 = nc * BKK;
                CP16(sb,             srcA + k0);
                CP16(sb + 16,        srcA + k0 + 8);
                CP16(sb + 32,        srcA + k0 + 16);
                CP16(sb + 48,        srcA + k0 + 24);
                CP16(sb + MATB,      srcB + k0);
                CP16(sb + MATB + 16, srcB + k0 + 8);
                CP16(sb + MATB + 32, srcB + k0 + 16);
                CP16(sb + MATB + 48, srcB + k0 + 24);
            }
            CP_COMMIT();
        }
        uint32_t st = sbase + (ch % STG) * STGB;
        uint32_t sA0 = st + aoff, sB0 = st + MATB + boff;
        #pragma unroll
        for (int kk = 0; kk < BKK; kk += 16) {
            uint32_t ah[2][4], bh[4][4];
            #pragma unroll
            for (int f = 0; f < 2; f++) {
                uint32_t o = (uint32_t)(f * 16 * SST + kk) * 2;
                LDSM_X4(ah[f][0], ah[f][1], ah[f][2], ah[f][3], sA0 + o);
            }
            #pragma unroll
            for (int q = 0; q < 4; q++) {
                uint32_t o = (uint32_t)(q * 16 * SST + kk) * 2;
                LDSM_X4(bh[q][0], bh[q][1], bh[q][2], bh[q][3], sB0 + o);
            }
            #pragma unroll
            for (int f = 0; f < 2; f++)
                #pragma unroll
                for (int g = 0; g < 8; g++) {
                    int q = g >> 1, s = g & 1;
                    MMA_F16(acc[f][g], ah[f][0], ah[f][1], ah[f][2], ah[f][3],
                            bh[q][s], bh[q][2 + s]);
                }
        }
    }
    // epilogue: + bv, store to g_V
    float bvv[8][2];
    #pragma unroll
    for (int g = 0; g < 8; g++) {
        int c = bn + wn * 64 + g * 8 + (lane & 3) * 2;
        bvv[g][0] = bv[c]; bvv[g][1] = bv[c + 1];
    }
    #pragma unroll
    for (int f = 0; f < 2; f++)
        #pragma unroll
        for (int g = 0; g < 8; g++) {
            int r = bm + wm * 32 + f * 16 + (lane >> 2);
            int c = bn + wn * 64 + g * 8 + (lane & 3) * 2;
            float2 v0, v1;
            v0.x = acc[f][g][0] + bvv[g][0]; v0.y = acc[f][g][1] + bvv[g][1];
            v1.x = acc[f][g][2] + bvv[g][0]; v1.y = acc[f][g][3] + bvv[g][1];
            *(float2*)(g_V + (size_t)r * Q_ + c) = v0;
            *(float2*)(g_V + (size_t)(r + 8) * Q_ + c) = v1;
        }
}

// ---------------- kernel 4: per-batch scan of s ------------------------------
__global__ void k_scan_s(float* __restrict__ out_w) {
    int b = blockIdx.x;
    int t = threadIdx.x;
    int lane = t & 31, warp = t >> 5;
    int base = b * S_ + t * 4;
    float s0 = g_s[base], s1 = g_s[base + 1], s2 = g_s[base + 2], s3 = g_s[base + 3];
    float e0 = expf(s0), e1 = expf(s1), e2 = expf(s2), e3 = expf(s3);
    float m0 = s0, m1 = fmaxf(m0, s1), m2 = fmaxf(m1, s2), m3 = fmaxf(m2, s3);
    float p0 = e0, p1 = p0 + e1, p2 = p1 + e2, p3 = p2 + e3;
    float tm = m3, tp = p3;
    #pragma unroll
    for (int o = 1; o < 32; o <<= 1) {
        float om = __shfl_up_sync(0xffffffffu, tm, o);
        float op = __shfl_up_sync(0xffffffffu, tp, o);
        if (lane >= o) { tm = fmaxf(tm, om); tp += op; }
    }
    float em = __shfl_up_sync(0xffffffffu, tm, 1);
    float ep = __shfl_up_sync(0xffffffffu, tp, 1);
    if (lane == 0) { em = -INFINITY; ep = 0.f; }
    __shared__ float wm[32], wp[32];
    if (lane == 31) { wm[warp] = tm; wp[warp] = tp; }
    __syncthreads();
    if (warp == 0) {
        float vm = wm[lane], vp = wp[lane];
        #pragma unroll
        for (int o = 1; o < 32; o <<= 1) {
            float om = __shfl_up_sync(0xffffffffu, vm, o);
            float op = __shfl_up_sync(0xffffffffu, vp, o);
            if (lane >= o) { vm = fmaxf(vm, om); vp += op; }
        }
        float xm = __shfl_up_sync(0xffffffffu, vm, 1);
        float xp = __shfl_up_sync(0xffffffffu, vp, 1);
        if (lane == 0) { xm = -INFINITY; xp = 0.f; }
        wm[lane] = xm; wp[lane] = xp;
    }
    __syncthreads();
    float exm = fmaxf(wm[warp], em);
    float exp_ = wp[warp] + ep;
    float M0 = fmaxf(exm, m0), M1 = fmaxf(exm, m1);
    float M2 = fmaxf(exm, m2), M3 = fmaxf(exm, m3);
    float P0 = exp_ + p0, P1 = exp_ + p1, P2 = exp_ + p2, P3 = exp_ + p3;
    float c0 = expf(-M0), c1 = expf(-M1), c2 = expf(-M2), c3 = expf(-M3);
    g_e[base] = e0; g_e[base + 1] = e1; g_e[base + 2] = e2; g_e[base + 3] = e3;
    g_coef[base] = c0; g_coef[base + 1] = c1; g_coef[base + 2] = c2; g_coef[base + 3] = c3;
    int wb = b * S_ + t * 4;
    out_w[wb] = P0 * c0; out_w[wb + 1] = P1 * c1;
    out_w[wb + 2] = P2 * c2; out_w[wb + 3] = P3 * c3;
}

// ---------------- kernel 5: chunk partial sums of e_i * V_i ------------------
__global__ void k_pass1() {
    int b = blockIdx.y, c = blockIdx.x;
    int t = threadIdx.x;
    __shared__ float se[CH];
    if (t < CH) se[t] = g_e[b * S_ + c * CH + t];
    __syncthreads();
    float4 acc = make_float4(0.f, 0.f, 0.f, 0.f);
    const float4* vp = (const float4*)(g_V + (size_t)(b * S_ + c * CH) * Q_) + t;
    #pragma unroll 4
    for (int i = 0; i < CH; i++) {
        float e = se[i];
        float4 v = vp[(size_t)i * (Q_ / 4)];
        acc.x += e * v.x; acc.y += e * v.y; acc.z += e * v.z; acc.w += e * v.w;
    }
    *((float4*)(g_part + (size_t)(b * NC + c) * Q_) + t) = acc;
}

// ---------------- kernel 6: exclusive scan of partials over chunks -----------
__global__ void k_cscan() {
    int b = blockIdx.x;
    int q = threadIdx.x;
    float run = 0.f;
    for (int c = 0; c < NC; c++) {
        float* p = g_part + (size_t)(b * NC + c) * Q_ + q;
        float v = *p;
        *p = run;
        run += v;
    }
}

// ---------------- kernel 7: final inclusive scan + normalize, write u --------
__global__ void k_pass2(float* __restrict__ out_u) {
    int b = blockIdx.y, c = blockIdx.x;
    int t = threadIdx.x;
    __shared__ float se[CH], scf[CH];
    if (t < CH) {
        int i = b * S_ + c * CH + t;
        se[t] = g_e[i];
        scf[t] = g_coef[i];
    }
    __syncthreads();
    float4 acc = *((const float4*)(g_part + (size_t)(b * NC + c) * Q_) + t);
    const float4* vp = (const float4*)(g_V + (size_t)(b * S_ + c * CH) * Q_) + t;
    float4* up = (float4*)(out_u + (size_t)(b * S_ + c * CH) * Q_) + t;
    #pragma unroll 4
    for (int i = 0; i < CH; i++) {
        float e = se[i];
        float4 v = vp[(size_t)i * (Q_ / 4)];
        acc.x += e * v.x; acc.y += e * v.y; acc.z += e * v.z; acc.w += e * v.w;
        float cf = scf[i];
        float4 o;
        o.x = acc.x * cf; o.y = acc.y * cf; o.z = acc.z * cf; o.w = acc.w * cf;
        up[(size_t)i * (Q_ / 4)] = o;
    }
}

// ---------------- launch -----------------------------------------------------
extern "C" void kernel_launch(void* const* d_in, const int* in_sizes, int n_in,
                              void* d_out, int out_size) {
    const int*   ids   = (const int*)d_in[0];
    const float* emb   = (const float*)d_in[1];
    const float* Wk    = (const float*)d_in[2];
    const float* bk    = (const float*)d_in[3];
    const float* Wv    = (const float*)d_in[4];
    const float* bv    = (const float*)d_in[5];
    const float* query = (const float*)d_in[6];
    float* out   = (float*)d_out;
    float* out_u = out;                          // [B,S,Q]
    float* out_w = out + (size_t)BS_ * Q_;       // [B,S,1]

    cudaFuncSetAttribute(k_gemm_mma,
                         cudaFuncAttributeMaxDynamicSharedMemorySize, STG * STGB);

    k_wkq     <<<D_ + 1, 256>>>(Wk, bk, query);
    k_ascore  <<<BS_ / 2, 256>>>(emb, ids);
    k_wt      <<<dim3(Q_ / 32, D_ / 32), dim3(32, 8)>>>(Wv);
    k_gemm_mma<<<dim3(Q_ / 128, BS_ / 128), 256, STG * STGB>>>(bv);
    k_scan_s  <<<B_, 1024>>>(out_w);
    k_pass1   <<<dim3(NC, B_), 256>>>();
    k_cscan   <<<B_, 1024>>>();
    k_pass2   <<<dim3(NC, B_), 256>>>(out_u);
}

// round 11
// speedup vs baseline: 1.2280x; 1.2280x over previous
#include <cuda_runtime.h>
#include <cuda_fp16.h>
#include <math.h>
#include <stdint.h>

#define B_ 4
#define S_ 4096
#define BS_ (B_*S_)      // 16384 tokens
#define D_ 1024
#define Q_ 1024
#define CH 64            // scan chunk length
#define NC (S_/CH)       // 64 chunks per batch

// ---------------- scratch (static device globals; no cudaMalloc allowed) ----
__device__ __align__(128) __half g_V[BS_*Q_];       // 32 MB: V = emb@Wv + bv (fp16)
__device__ __align__(128) float g_part[B_*NC*Q_];   // 1 MB: chunk partial sums
__device__ float g_s[BS_];
__device__ float g_e[BS_];                          // exp(s)
__device__ float g_coef[BS_];                       // exp(-prefix_max)
__device__ float g_wkq[D_];                         // Wk @ query^T
__device__ float g_skq;                             // bk . query
__device__ __align__(128) __half g_wt_h[Q_*D_];     // Wv^T fp16 [n][k]
__device__ __align__(128) __half g_a_h[BS_*D_];     // gathered emb fp16 [m][k]

// ---------------- helpers ----------------------------------------------------
__device__ __forceinline__ uint32_t smem_u32(const void* p) {
    uint32_t a;
    asm("{ .reg .u64 t; cvta.to.shared.u64 t, %1; cvt.u32.u64 %0, t; }"
        : "=r"(a) : "l"(p));
    return a;
}
static __device__ __forceinline__ uint32_t pack_h2(float x, float y) {
    __half2 h = __floats2half2_rn(x, y);
    return *(uint32_t*)&h;
}
#define LDSM_X4(r0, r1, r2, r3, addr) \
    asm volatile("ldmatrix.sync.aligned.m8n8.x4.shared.b16 {%0,%1,%2,%3}, [%4];" \
                 : "=r"(r0), "=r"(r1), "=r"(r2), "=r"(r3) : "r"(addr))
#define MMA_F16(d, a0, a1, a2, a3, b0, b1) \
    asm volatile("mma.sync.aligned.m16n8k16.row.col.f32.f16.f16.f32 " \
                 "{%0,%1,%2,%3}, {%4,%5,%6,%7}, {%8,%9}, {%0,%1,%2,%3};" \
                 : "+f"((d)[0]), "+f"((d)[1]), "+f"((d)[2]), "+f"((d)[3]) \
                 : "r"(a0), "r"(a1), "r"(a2), "r"(a3), "r"(b0), "r"(b1))
#define CP16(dst, src) \
    asm volatile("cp.async.cg.shared.global [%0], [%1], 16;" \
                 :: "r"(dst), "l"(src) : "memory")
#define CP_COMMIT() asm volatile("cp.async.commit_group;" ::: "memory")
#define CP_WAIT(n)  asm volatile("cp.async.wait_group %0;" :: "n"(n) : "memory")

// ---------------- kernel 1: wkq[d] = Wk[d,:] . query ;  skq = bk . query ----
__global__ void k_wkq(const float* __restrict__ Wk, const float* __restrict__ bk,
                      const float* __restrict__ query) {
    __shared__ float red[256];
    int d = blockIdx.x;
    const float* row = (d < D_) ? (Wk + (size_t)d * Q_) : bk;
    float acc = 0.f;
    for (int q = threadIdx.x; q < Q_; q += 256) acc += row[q] * query[q];
    red[threadIdx.x] = acc;
    __syncthreads();
    for (int s = 128; s > 0; s >>= 1) {
        if (threadIdx.x < s) red[threadIdx.x] += red[threadIdx.x + s];
        __syncthreads();
    }
    if (threadIdx.x == 0) {
        if (d < D_) g_wkq[d] = red[0]; else g_skq = red[0];
    }
}

// ---------------- kernel 2: fused gather+fp16 convert+score ------------------
// block = 256 threads = 2 rows (128 threads/row, 8 floats each)
__global__ void k_ascore(const float* __restrict__ emb, const int* __restrict__ ids) {
    __shared__ float swkq[D_];
    __shared__ float red[8];
    int tid = threadIdx.x;
    for (int i = tid; i < D_; i += 256) swkq[i] = g_wkq[i];
    __syncthreads();
    int m = blockIdx.x * 2 + (tid >> 7);
    int col = (tid & 127) * 8;
    const float* src = emb + (size_t)ids[m] * D_ + col;
    float4 x = ((const float4*)src)[0];
    float4 y = ((const float4*)src)[1];
    uint4 hv = make_uint4(pack_h2(x.x, x.y), pack_h2(x.z, x.w),
                          pack_h2(y.x, y.y), pack_h2(y.z, y.w));
    *(uint4*)(g_a_h + (size_t)m * D_ + col) = hv;
    float acc = x.x * swkq[col]     + x.y * swkq[col + 1]
              + x.z * swkq[col + 2] + x.w * swkq[col + 3]
              + y.x * swkq[col + 4] + y.y * swkq[col + 5]
              + y.z * swkq[col + 6] + y.w * swkq[col + 7];
    #pragma unroll
    for (int o = 16; o > 0; o >>= 1) acc += __shfl_xor_sync(0xffffffffu, acc, o);
    int warp = tid >> 5;
    if ((tid & 31) == 0) red[warp] = acc;
    __syncthreads();
    if ((tid & 127) == 0) {
        int base = (tid >> 7) * 4;
        g_s[m] = red[base] + red[base + 1] + red[base + 2] + red[base + 3] + g_skq;
    }
}

// ---------------- kernel 2b: transpose + convert Wv -> Wt fp16 [n][k] --------
__global__ void k_wt(const float* __restrict__ Wv) {
    __shared__ float tile[32][33];
    int kb = blockIdx.y * 32, nb = blockIdx.x * 32;
    int tx = threadIdx.x, ty = threadIdx.y;          // 32 x 8
    #pragma unroll
    for (int j = 0; j < 32; j += 8)
        tile[ty + j][tx] = Wv[(size_t)(kb + ty + j) * Q_ + nb + tx];
    __syncthreads();
    #pragma unroll
    for (int j = 0; j < 32; j += 8) {
        float v = tile[tx][ty + j];                   // = Wv[kb+tx][nb+ty+j]
        g_wt_h[(size_t)(nb + ty + j) * D_ + kb + tx] = __float2half_rn(v);
    }
}

// ---------------- kernel 3: fp16 single-MMA GEMM with cp.async pipeline ------
// CTA 128x128, BK=32, 4 stages. 8 warps each 32(M)x64(N). Padded stride 40.
#define SST 40
#define STG 4
#define MATB (128 * SST * 2)              // bytes per matrix per stage (10240)
#define STGB (2 * MATB)                   // bytes per stage (20480)
#define NCHK (D_ / 32)                    // 32 K-chunks

__global__ __launch_bounds__(256, 2) void k_gemm_mma(const float* __restrict__ bv) {
    extern __shared__ __align__(16) char smraw[];
    uint32_t sbase = smem_u32(smraw);
    int tid = threadIdx.x, lane = tid & 31, wid = tid >> 5;
    int wm = wid & 3, wn = wid >> 2;
    int bm = blockIdx.y * 128, bn = blockIdx.x * 128;
    int lrow = tid >> 1, lhalf = (tid & 1) * 16;     // loader: row, k-half

    const __half* srcA = g_a_h + (size_t)(bm + lrow) * D_ + lhalf;
    const __half* srcB = g_wt_h + (size_t)(bn + lrow) * D_ + lhalf;
    uint32_t dsto = (uint32_t)(lrow * SST + lhalf) * 2;  // byte offset in matrix

    uint32_t aoff = (uint32_t)((wm * 32 + (lane & 15)) * SST + (lane >> 4) * 8) * 2;
    uint32_t boff = (uint32_t)((wn * 64 + (lane & 15)) * SST + (lane >> 4) * 8) * 2;

    float acc[2][8][4];
    #pragma unroll
    for (int f = 0; f < 2; f++)
        #pragma unroll
        for (int g = 0; g < 8; g++)
            #pragma unroll
            for (int v = 0; v < 4; v++) acc[f][g][v] = 0.f;

    // prologue: fill STG-1 stages
    #pragma unroll
    for (int s = 0; s < STG - 1; s++) {
        uint32_t sb = sbase + s * STGB + dsto;
        int k0 = s * 32;
        CP16(sb,             srcA + k0);
        CP16(sb + 16,        srcA + k0 + 8);
        CP16(sb + MATB,      srcB + k0);
        CP16(sb + MATB + 16, srcB + k0 + 8);
        CP_COMMIT();
    }

    for (int ch = 0; ch < NCHK; ch++) {
        CP_WAIT(STG - 2);
        __syncthreads();
        // issue loads for chunk ch+STG-1 (overlap with compute below)
        {
            int nc = ch + STG - 1;
            if (nc < NCHK) {
                uint32_t sb = sbase + (nc % STG) * STGB + dsto;
                int k0 = nc * 32;
                CP16(sb,             srcA + k0);
                CP16(sb + 16,        srcA + k0 + 8);
                CP16(sb + MATB,      srcB + k0);
                CP16(sb + MATB + 16, srcB + k0 + 8);
            }
            CP_COMMIT();
        }
        uint32_t st = sbase + (ch % STG) * STGB;
        uint32_t sA0 = st + aoff, sB0 = st + MATB + boff;
        #pragma unroll
        for (int kk = 0; kk < 32; kk += 16) {
            uint32_t ah[2][4], bh[4][4];
            #pragma unroll
            for (int f = 0; f < 2; f++) {
                uint32_t o = (uint32_t)(f * 16 * SST + kk) * 2;
                LDSM_X4(ah[f][0], ah[f][1], ah[f][2], ah[f][3], sA0 + o);
            }
            #pragma unroll
            for (int q = 0; q < 4; q++) {
                uint32_t o = (uint32_t)(q * 16 * SST + kk) * 2;
                LDSM_X4(bh[q][0], bh[q][1], bh[q][2], bh[q][3], sB0 + o);
            }
            #pragma unroll
            for (int f = 0; f < 2; f++)
                #pragma unroll
                for (int g = 0; g < 8; g++) {
                    int q = g >> 1, s = g & 1;
                    MMA_F16(acc[f][g], ah[f][0], ah[f][1], ah[f][2], ah[f][3],
                            bh[q][s], bh[q][2 + s]);
                }
        }
    }
    // epilogue: + bv, convert to fp16, store to g_V
    float bvv[8][2];
    #pragma unroll
    for (int g = 0; g < 8; g++) {
        int c = bn + wn * 64 + g * 8 + (lane & 3) * 2;
        bvv[g][0] = bv[c]; bvv[g][1] = bv[c + 1];
    }
    #pragma unroll
    for (int f = 0; f < 2; f++)
        #pragma unroll
        for (int g = 0; g < 8; g++) {
            int r = bm + wm * 32 + f * 16 + (lane >> 2);
            int c = bn + wn * 64 + g * 8 + (lane & 3) * 2;
            uint32_t v0 = pack_h2(acc[f][g][0] + bvv[g][0], acc[f][g][1] + bvv[g][1]);
            uint32_t v1 = pack_h2(acc[f][g][2] + bvv[g][0], acc[f][g][3] + bvv[g][1]);
            *(uint32_t*)(g_V + (size_t)r * Q_ + c) = v0;
            *(uint32_t*)(g_V + (size_t)(r + 8) * Q_ + c) = v1;
        }
}

// ---------------- kernel 4: per-batch scan of s ------------------------------
__global__ void k_scan_s(float* __restrict__ out_w) {
    int b = blockIdx.x;
    int t = threadIdx.x;
    int lane = t & 31, warp = t >> 5;
    int base = b * S_ + t * 4;
    float s0 = g_s[base], s1 = g_s[base + 1], s2 = g_s[base + 2], s3 = g_s[base + 3];
    float e0 = expf(s0), e1 = expf(s1), e2 = expf(s2), e3 = expf(s3);
    float m0 = s0, m1 = fmaxf(m0, s1), m2 = fmaxf(m1, s2), m3 = fmaxf(m2, s3);
    float p0 = e0, p1 = p0 + e1, p2 = p1 + e2, p3 = p2 + e3;
    float tm = m3, tp = p3;
    #pragma unroll
    for (int o = 1; o < 32; o <<= 1) {
        float om = __shfl_up_sync(0xffffffffu, tm, o);
        float op = __shfl_up_sync(0xffffffffu, tp, o);
        if (lane >= o) { tm = fmaxf(tm, om); tp += op; }
    }
    float em = __shfl_up_sync(0xffffffffu, tm, 1);
    float ep = __shfl_up_sync(0xffffffffu, tp, 1);
    if (lane == 0) { em = -INFINITY; ep = 0.f; }
    __shared__ float wm[32], wp[32];
    if (lane == 31) { wm[warp] = tm; wp[warp] = tp; }
    __syncthreads();
    if (warp == 0) {
        float vm = wm[lane], vp = wp[lane];
        #pragma unroll
        for (int o = 1; o < 32; o <<= 1) {
            float om = __shfl_up_sync(0xffffffffu, vm, o);
            float op = __shfl_up_sync(0xffffffffu, vp, o);
            if (lane >= o) { vm = fmaxf(vm, om); vp += op; }
        }
        float xm = __shfl_up_sync(0xffffffffu, vm, 1);
        float xp = __shfl_up_sync(0xffffffffu, vp, 1);
        if (lane == 0) { xm = -INFINITY; xp = 0.f; }
        wm[lane] = xm; wp[lane] = xp;
    }
    __syncthreads();
    float exm = fmaxf(wm[warp], em);
    float exp_ = wp[warp] + ep;
    float M0 = fmaxf(exm, m0), M1 = fmaxf(exm, m1);
    float M2 = fmaxf(exm, m2), M3 = fmaxf(exm, m3);
    float P0 = exp_ + p0, P1 = exp_ + p1, P2 = exp_ + p2, P3 = exp_ + p3;
    float c0 = expf(-M0), c1 = expf(-M1), c2 = expf(-M2), c3 = expf(-M3);
    g_e[base] = e0; g_e[base + 1] = e1; g_e[base + 2] = e2; g_e[base + 3] = e3;
    g_coef[base] = c0; g_coef[base + 1] = c1; g_coef[base + 2] = c2; g_coef[base + 3] = c3;
    int wb = b * S_ + t * 4;
    out_w[wb] = P0 * c0; out_w[wb + 1] = P1 * c1;
    out_w[wb + 2] = P2 * c2; out_w[wb + 3] = P3 * c3;
}

// ---------------- kernel 5: chunk partial sums of e_i * V_i (V fp16) ---------
__global__ void k_pass1() {
    int b = blockIdx.y, c = blockIdx.x;
    int t = threadIdx.x;                  // 256 threads x 4 cols
    __shared__ float se[CH];
    if (t < CH) se[t] = g_e[b * S_ + c * CH + t];
    __syncthreads();
    float4 acc = make_float4(0.f, 0.f, 0.f, 0.f);
    const uint2* vp = (const uint2*)(g_V + (size_t)(b * S_ + c * CH) * Q_) + t;
    #pragma unroll 4
    for (int i = 0; i < CH; i++) {
        float e = se[i];
        uint2 v = vp[(size_t)i * (Q_ / 4)];
        float2 v01 = __half22float2(*(const __half2*)&v.x);
        float2 v23 = __half22float2(*(const __half2*)&v.y);
        acc.x += e * v01.x; acc.y += e * v01.y;
        acc.z += e * v23.x; acc.w += e * v23.y;
    }
    *((float4*)(g_part + (size_t)(b * NC + c) * Q_) + t) = acc;
}

// ---------------- kernel 6: exclusive scan of partials over chunks -----------
__global__ void k_cscan() {
    int b = blockIdx.x;
    int q = threadIdx.x;
    float run = 0.f;
    for (int c = 0; c < NC; c++) {
        float* p = g_part + (size_t)(b * NC + c) * Q_ + q;
        float v = *p;
        *p = run;
        run += v;
    }
}

// ---------------- kernel 7: final inclusive scan + normalize, write u --------
__global__ void k_pass2(float* __restrict__ out_u) {
    int b = blockIdx.y, c = blockIdx.x;
    int t = threadIdx.x;
    __shared__ float se[CH], scf[CH];
    if (t < CH) {
        int i = b * S_ + c * CH + t;
        se[t] = g_e[i];
        scf[t] = g_coef[i];
    }
    __syncthreads();
    float4 acc = *((const float4*)(g_part + (size_t)(b * NC + c) * Q_) + t);
    const uint2* vp = (const uint2*)(g_V + (size_t)(b * S_ + c * CH) * Q_) + t;
    float4* up = (float4*)(out_u + (size_t)(b * S_ + c * CH) * Q_) + t;
    #pragma unroll 4
    for (int i = 0; i < CH; i++) {
        float e = se[i];
        uint2 v = vp[(size_t)i * (Q_ / 4)];
        float2 v01 = __half22float2(*(const __half2*)&v.x);
        float2 v23 = __half22float2(*(const __half2*)&v.y);
        acc.x += e * v01.x; acc.y += e * v01.y;
        acc.z += e * v23.x; acc.w += e * v23.y;
        float cf = scf[i];
        float4 o;
        o.x = acc.x * cf; o.y = acc.y * cf; o.z = acc.z * cf; o.w = acc.w * cf;
        up[(size_t)i * (Q_ / 4)] = o;
    }
}

// ---------------- launch -----------------------------------------------------
extern "C" void kernel_launch(void* const* d_in, const int* in_sizes, int n_in,
                              void* d_out, int out_size) {
    const int*   ids   = (const int*)d_in[0];
    const float* emb   = (const float*)d_in[1];
    const float* Wk    = (const float*)d_in[2];
    const float* bk    = (const float*)d_in[3];
    const float* Wv    = (const float*)d_in[4];
    const float* bv    = (const float*)d_in[5];
    const float* query = (const float*)d_in[6];
    float* out   = (float*)d_out;
    float* out_u = out;                          // [B,S,Q]
    float* out_w = out + (size_t)BS_ * Q_;       // [B,S,1]

    cudaFuncSetAttribute(k_gemm_mma,
                         cudaFuncAttributeMaxDynamicSharedMemorySize, STG * STGB);

    k_wkq     <<<D_ + 1, 256>>>(Wk, bk, query);
    k_ascore  <<<BS_ / 2, 256>>>(emb, ids);
    k_wt      <<<dim3(Q_ / 32, D_ / 32), dim3(32, 8)>>>(Wv);
    k_gemm_mma<<<dim3(Q_ / 128, BS_ / 128), 256, STG * STGB>>>(bv);
    k_scan_s  <<<B_, 1024>>>(out_w);
    k_pass1   <<<dim3(NC, B_), 256>>>();
    k_cscan   <<<B_, 1024>>>();
    k_pass2   <<<dim3(NC, B_), 256>>>(out_u);
}

// round 12
// speedup vs baseline: 1.2763x; 1.0393x over previous
#include <cuda_runtime.h>
#include <cuda_fp16.h>
#include <math.h>
#include <stdint.h>

#define B_ 4
#define S_ 4096
#define BS_ (B_*S_)      // 16384 tokens
#define D_ 1024
#define Q_ 1024
#define CH 64            // scan chunk length
#define NC (S_/CH)       // 64 chunks per batch

// ---------------- scratch (static device globals; no cudaMalloc allowed) ----
__device__ __align__(128) __half g_V[BS_*Q_];       // 32 MB: V = emb@Wv + bv (fp16)
__device__ __align__(128) float g_part[B_*NC*Q_];   // 1 MB: chunk partial sums
__device__ float g_s[BS_];
__device__ float g_e[BS_];                          // exp(s)
__device__ float g_coef[BS_];                       // exp(-prefix_max)
__device__ float g_wkq[D_];                         // Wk @ query^T
__device__ float g_skq;                             // bk . query
__device__ __align__(128) __half g_wt_h[Q_*D_];     // Wv^T fp16 [n][k]
__device__ __align__(128) __half g_a_h[BS_*D_];     // gathered emb fp16 [m][k]

// ---------------- helpers ----------------------------------------------------
__device__ __forceinline__ uint32_t smem_u32(const void* p) {
    uint32_t a;
    asm("{ .reg .u64 t; cvta.to.shared.u64 t, %1; cvt.u32.u64 %0, t; }"
        : "=r"(a) : "l"(p));
    return a;
}
static __device__ __forceinline__ uint32_t pack_h2(float x, float y) {
    __half2 h = __floats2half2_rn(x, y);
    return *(uint32_t*)&h;
}
#define LDSM_X4(r0, r1, r2, r3, addr) \
    asm volatile("ldmatrix.sync.aligned.m8n8.x4.shared.b16 {%0,%1,%2,%3}, [%4];" \
                 : "=r"(r0), "=r"(r1), "=r"(r2), "=r"(r3) : "r"(addr))
#define MMA_F16(d, a0, a1, a2, a3, b0, b1) \
    asm volatile("mma.sync.aligned.m16n8k16.row.col.f32.f16.f16.f32 " \
                 "{%0,%1,%2,%3}, {%4,%5,%6,%7}, {%8,%9}, {%0,%1,%2,%3};" \
                 : "+f"((d)[0]), "+f"((d)[1]), "+f"((d)[2]), "+f"((d)[3]) \
                 : "r"(a0), "r"(a1), "r"(a2), "r"(a3), "r"(b0), "r"(b1))
#define CP16(dst, src) \
    asm volatile("cp.async.cg.shared.global [%0], [%1], 16;" \
                 :: "r"(dst), "l"(src) : "memory")
#define CP_COMMIT() asm volatile("cp.async.commit_group;" ::: "memory")
#define CP_WAIT(n)  asm volatile("cp.async.wait_group %0;" :: "n"(n) : "memory")

// ---------------- kernel 1: wkq[d] = Wk[d,:] . query ;  skq = bk . query ----
__global__ void k_wkq(const float* __restrict__ Wk, const float* __restrict__ bk,
                      const float* __restrict__ query) {
    __shared__ float red[256];
    int d = blockIdx.x;
    const float* row = (d < D_) ? (Wk + (size_t)d * Q_) : bk;
    float acc = 0.f;
    for (int q = threadIdx.x; q < Q_; q += 256) acc += row[q] * query[q];
    red[threadIdx.x] = acc;
    __syncthreads();
    for (int s = 128; s > 0; s >>= 1) {
        if (threadIdx.x < s) red[threadIdx.x] += red[threadIdx.x + s];
        __syncthreads();
    }
    if (threadIdx.x == 0) {
        if (d < D_) g_wkq[d] = red[0]; else g_skq = red[0];
    }
}

// ---------------- kernel 2: fused gather+fp16 convert+score ------------------
// block = 256 threads = 2 rows (128 threads/row, 8 floats each)
__global__ void k_ascore(const float* __restrict__ emb, const int* __restrict__ ids) {
    __shared__ float swkq[D_];
    __shared__ float red[8];
    int tid = threadIdx.x;
    for (int i = tid; i < D_; i += 256) swkq[i] = g_wkq[i];
    __syncthreads();
    int m = blockIdx.x * 2 + (tid >> 7);
    int col = (tid & 127) * 8;
    const float* src = emb + (size_t)ids[m] * D_ + col;
    float4 x = ((const float4*)src)[0];
    float4 y = ((const float4*)src)[1];
    uint4 hv = make_uint4(pack_h2(x.x, x.y), pack_h2(x.z, x.w),
                          pack_h2(y.x, y.y), pack_h2(y.z, y.w));
    *(uint4*)(g_a_h + (size_t)m * D_ + col) = hv;
    float acc = x.x * swkq[col]     + x.y * swkq[col + 1]
              + x.z * swkq[col + 2] + x.w * swkq[col + 3]
              + y.x * swkq[col + 4] + y.y * swkq[col + 5]
              + y.z * swkq[col + 6] + y.w * swkq[col + 7];
    #pragma unroll
    for (int o = 16; o > 0; o >>= 1) acc += __shfl_xor_sync(0xffffffffu, acc, o);
    int warp = tid >> 5;
    if ((tid & 31) == 0) red[warp] = acc;
    __syncthreads();
    if ((tid & 127) == 0) {
        int base = (tid >> 7) * 4;
        g_s[m] = red[base] + red[base + 1] + red[base + 2] + red[base + 3] + g_skq;
    }
}

// ---------------- kernel 2b: transpose + convert Wv -> Wt fp16 [n][k] --------
__global__ void k_wt(const float* __restrict__ Wv) {
    __shared__ float tile[32][33];
    int kb = blockIdx.y * 32, nb = blockIdx.x * 32;
    int tx = threadIdx.x, ty = threadIdx.y;          // 32 x 8
    #pragma unroll
    for (int j = 0; j < 32; j += 8)
        tile[ty + j][tx] = Wv[(size_t)(kb + ty + j) * Q_ + nb + tx];
    __syncthreads();
    #pragma unroll
    for (int j = 0; j < 32; j += 8) {
        float v = tile[tx][ty + j];                   // = Wv[kb+tx][nb+ty+j]
        g_wt_h[(size_t)(nb + ty + j) * D_ + kb + tx] = __float2half_rn(v);
    }
}

// ---------------- kernel 3: fp16 single-MMA GEMM with cp.async pipeline ------
// CTA 128x128, BK=32, 4 stages. 8 warps each 32(M)x64(N). Padded stride 40.
#define SST 40
#define STG 4
#define MATB (128 * SST * 2)              // bytes per matrix per stage (10240)
#define STGB (2 * MATB)                   // bytes per stage (20480)
#define NCHK (D_ / 32)                    // 32 K-chunks

__global__ __launch_bounds__(256, 2) void k_gemm_mma(const float* __restrict__ bv) {
    extern __shared__ __align__(16) char smraw[];
    uint32_t sbase = smem_u32(smraw);
    int tid = threadIdx.x, lane = tid & 31, wid = tid >> 5;
    int wm = wid & 3, wn = wid >> 2;
    int bm = blockIdx.y * 128, bn = blockIdx.x * 128;
    int lrow = tid >> 1, lhalf = (tid & 1) * 16;     // loader: row, k-half

    const __half* srcA = g_a_h + (size_t)(bm + lrow) * D_ + lhalf;
    const __half* srcB = g_wt_h + (size_t)(bn + lrow) * D_ + lhalf;
    uint32_t dsto = (uint32_t)(lrow * SST + lhalf) * 2;  // byte offset in matrix

    uint32_t aoff = (uint32_t)((wm * 32 + (lane & 15)) * SST + (lane >> 4) * 8) * 2;
    uint32_t boff = (uint32_t)((wn * 64 + (lane & 15)) * SST + (lane >> 4) * 8) * 2;

    float acc[2][8][4];
    #pragma unroll
    for (int f = 0; f < 2; f++)
        #pragma unroll
        for (int g = 0; g < 8; g++)
            #pragma unroll
            for (int v = 0; v < 4; v++) acc[f][g][v] = 0.f;

    // prologue: fill STG-1 stages
    #pragma unroll
    for (int s = 0; s < STG - 1; s++) {
        uint32_t sb = sbase + s * STGB + dsto;
        int k0 = s * 32;
        CP16(sb,             srcA + k0);
        CP16(sb + 16,        srcA + k0 + 8);
        CP16(sb + MATB,      srcB + k0);
        CP16(sb + MATB + 16, srcB + k0 + 8);
        CP_COMMIT();
    }

    for (int ch = 0; ch < NCHK; ch++) {
        CP_WAIT(STG - 2);
        __syncthreads();
        // issue loads for chunk ch+STG-1 (overlap with compute below)
        {
            int nc = ch + STG - 1;
            if (nc < NCHK) {
                uint32_t sb = sbase + (nc % STG) * STGB + dsto;
                int k0 = nc * 32;
                CP16(sb,             srcA + k0);
                CP16(sb + 16,        srcA + k0 + 8);
                CP16(sb + MATB,      srcB + k0);
                CP16(sb + MATB + 16, srcB + k0 + 8);
            }
            CP_COMMIT();
        }
        uint32_t st = sbase + (ch % STG) * STGB;
        uint32_t sA0 = st + aoff, sB0 = st + MATB + boff;
        #pragma unroll
        for (int kk = 0; kk < 32; kk += 16) {
            uint32_t ah[2][4], bh[4][4];
            #pragma unroll
            for (int f = 0; f < 2; f++) {
                uint32_t o = (uint32_t)(f * 16 * SST + kk) * 2;
                LDSM_X4(ah[f][0], ah[f][1], ah[f][2], ah[f][3], sA0 + o);
            }
            #pragma unroll
            for (int q = 0; q < 4; q++) {
                uint32_t o = (uint32_t)(q * 16 * SST + kk) * 2;
                LDSM_X4(bh[q][0], bh[q][1], bh[q][2], bh[q][3], sB0 + o);
            }
            #pragma unroll
            for (int f = 0; f < 2; f++)
                #pragma unroll
                for (int g = 0; g < 8; g++) {
                    int q = g >> 1, s = g & 1;
                    MMA_F16(acc[f][g], ah[f][0], ah[f][1], ah[f][2], ah[f][3],
                            bh[q][s], bh[q][2 + s]);
                }
        }
    }
    // epilogue: + bv, convert to fp16, store to g_V
    float bvv[8][2];
    #pragma unroll
    for (int g = 0; g < 8; g++) {
        int c = bn + wn * 64 + g * 8 + (lane & 3) * 2;
        bvv[g][0] = bv[c]; bvv[g][1] = bv[c + 1];
    }
    #pragma unroll
    for (int f = 0; f < 2; f++)
        #pragma unroll
        for (int g = 0; g < 8; g++) {
            int r = bm + wm * 32 + f * 16 + (lane >> 2);
            int c = bn + wn * 64 + g * 8 + (lane & 3) * 2;
            uint32_t v0 = pack_h2(acc[f][g][0] + bvv[g][0], acc[f][g][1] + bvv[g][1]);
            uint32_t v1 = pack_h2(acc[f][g][2] + bvv[g][0], acc[f][g][3] + bvv[g][1]);
            *(uint32_t*)(g_V + (size_t)r * Q_ + c) = v0;
            *(uint32_t*)(g_V + (size_t)(r + 8) * Q_ + c) = v1;
        }
}

// ---------------- kernel 4: per-batch scan of s ------------------------------
__global__ void k_scan_s(float* __restrict__ out_w) {
    int b = blockIdx.x;
    int t = threadIdx.x;
    int lane = t & 31, warp = t >> 5;
    int base = b * S_ + t * 4;
    float s0 = g_s[base], s1 = g_s[base + 1], s2 = g_s[base + 2], s3 = g_s[base + 3];
    float e0 = expf(s0), e1 = expf(s1), e2 = expf(s2), e3 = expf(s3);
    float m0 = s0, m1 = fmaxf(m0, s1), m2 = fmaxf(m1, s2), m3 = fmaxf(m2, s3);
    float p0 = e0, p1 = p0 + e1, p2 = p1 + e2, p3 = p2 + e3;
    float tm = m3, tp = p3;
    #pragma unroll
    for (int o = 1; o < 32; o <<= 1) {
        float om = __shfl_up_sync(0xffffffffu, tm, o);
        float op = __shfl_up_sync(0xffffffffu, tp, o);
        if (lane >= o) { tm = fmaxf(tm, om); tp += op; }
    }
    float em = __shfl_up_sync(0xffffffffu, tm, 1);
    float ep = __shfl_up_sync(0xffffffffu, tp, 1);
    if (lane == 0) { em = -INFINITY; ep = 0.f; }
    __shared__ float wm[32], wp[32];
    if (lane == 31) { wm[warp] = tm; wp[warp] = tp; }
    __syncthreads();
    if (warp == 0) {
        float vm = wm[lane], vp = wp[lane];
        #pragma unroll
        for (int o = 1; o < 32; o <<= 1) {
            float om = __shfl_up_sync(0xffffffffu, vm, o);
            float op = __shfl_up_sync(0xffffffffu, vp, o);
            if (lane >= o) { vm = fmaxf(vm, om); vp += op; }
        }
        float xm = __shfl_up_sync(0xffffffffu, vm, 1);
        float xp = __shfl_up_sync(0xffffffffu, vp, 1);
        if (lane == 0) { xm = -INFINITY; xp = 0.f; }
        wm[lane] = xm; wp[lane] = xp;
    }
    __syncthreads();
    float exm = fmaxf(wm[warp], em);
    float exp_ = wp[warp] + ep;
    float M0 = fmaxf(exm, m0), M1 = fmaxf(exm, m1);
    float M2 = fmaxf(exm, m2), M3 = fmaxf(exm, m3);
    float P0 = exp_ + p0, P1 = exp_ + p1, P2 = exp_ + p2, P3 = exp_ + p3;
    float c0 = expf(-M0), c1 = expf(-M1), c2 = expf(-M2), c3 = expf(-M3);
    g_e[base] = e0; g_e[base + 1] = e1; g_e[base + 2] = e2; g_e[base + 3] = e3;
    g_coef[base] = c0; g_coef[base + 1] = c1; g_coef[base + 2] = c2; g_coef[base + 3] = c3;
    int wb = b * S_ + t * 4;
    out_w[wb] = P0 * c0; out_w[wb + 1] = P1 * c1;
    out_w[wb + 2] = P2 * c2; out_w[wb + 3] = P3 * c3;
}

// ---------------- kernel 5: chunk partial sums of e_i * V_i (V fp16) ---------
__global__ void k_pass1() {
    int b = blockIdx.y, c = blockIdx.x;
    int t = threadIdx.x;                  // 256 threads x 4 cols
    __shared__ float se[CH];
    if (t < CH) se[t] = g_e[b * S_ + c * CH + t];
    __syncthreads();
    float4 acc = make_float4(0.f, 0.f, 0.f, 0.f);
    const uint2* vp = (const uint2*)(g_V + (size_t)(b * S_ + c * CH) * Q_) + t;
    #pragma unroll 4
    for (int i = 0; i < CH; i++) {
        float e = se[i];
        uint2 v = vp[(size_t)i * (Q_ / 4)];
        float2 v01 = __half22float2(*(const __half2*)&v.x);
        float2 v23 = __half22float2(*(const __half2*)&v.y);
        acc.x += e * v01.x; acc.y += e * v01.y;
        acc.z += e * v23.x; acc.w += e * v23.y;
    }
    *((float4*)(g_part + (size_t)(b * NC + c) * Q_) + t) = acc;
}

// ---------------- kernel 6: exclusive scan of partials over chunks -----------
// one thread per (b, q); all 64 chunk values loaded into registers first
// (independent loads, MLP=64), scanned in-register, written back.
// grid = B_ * (Q_/128) = 32 blocks of 128 threads (spread over 32 SMs).
__global__ void k_cscan() {
    int b = blockIdx.x >> 3;                       // 8 blocks per batch
    int q = (blockIdx.x & 7) * 128 + threadIdx.x;
    float v[NC];
    #pragma unroll
    for (int c = 0; c < NC; c++)
        v[c] = g_part[(size_t)(b * NC + c) * Q_ + q];
    float run = 0.f;
    #pragma unroll
    for (int c = 0; c < NC; c++) {
        float t = v[c];
        v[c] = run;
        run += t;
    }
    #pragma unroll
    for (int c = 0; c < NC; c++)
        g_part[(size_t)(b * NC + c) * Q_ + q] = v[c];
}

// ---------------- kernel 7: final inclusive scan + normalize, write u --------
__global__ void k_pass2(float* __restrict__ out_u) {
    int b = blockIdx.y, c = blockIdx.x;
    int t = threadIdx.x;
    __shared__ float se[CH], scf[CH];
    if (t < CH) {
        int i = b * S_ + c * CH + t;
        se[t] = g_e[i];
        scf[t] = g_coef[i];
    }
    __syncthreads();
    float4 acc = *((const float4*)(g_part + (size_t)(b * NC + c) * Q_) + t);
    const uint2* vp = (const uint2*)(g_V + (size_t)(b * S_ + c * CH) * Q_) + t;
    float4* up = (float4*)(out_u + (size_t)(b * S_ + c * CH) * Q_) + t;
    #pragma unroll 4
    for (int i = 0; i < CH; i++) {
        float e = se[i];
        uint2 v = vp[(size_t)i * (Q_ / 4)];
        float2 v01 = __half22float2(*(const __half2*)&v.x);
        float2 v23 = __half22float2(*(const __half2*)&v.y);
        acc.x += e * v01.x; acc.y += e * v01.y;
        acc.z += e * v23.x; acc.w += e * v23.y;
        float cf = scf[i];
        float4 o;
        o.x = acc.x * cf; o.y = acc.y * cf; o.z = acc.z * cf; o.w = acc.w * cf;
        up[(size_t)i * (Q_ / 4)] = o;
    }
}

// ---------------- launch -----------------------------------------------------
extern "C" void kernel_launch(void* const* d_in, const int* in_sizes, int n_in,
                              void* d_out, int out_size) {
    const int*   ids   = (const int*)d_in[0];
    const float* emb   = (const float*)d_in[1];
    const float* Wk    = (const float*)d_in[2];
    const float* bk    = (const float*)d_in[3];
    const float* Wv    = (const float*)d_in[4];
    const float* bv    = (const float*)d_in[5];
    const float* query = (const float*)d_in[6];
    float* out   = (float*)d_out;
    float* out_u = out;                          // [B,S,Q]
    float* out_w = out + (size_t)BS_ * Q_;       // [B,S,1]

    cudaFuncSetAttribute(k_gemm_mma,
                         cudaFuncAttributeMaxDynamicSharedMemorySize, STG * STGB);

    k_wkq     <<<D_ + 1, 256>>>(Wk, bk, query);
    k_ascore  <<<BS_ / 2, 256>>>(emb, ids);
    k_wt      <<<dim3(Q_ / 32, D_ / 32), dim3(32, 8)>>>(Wv);
    k_gemm_mma<<<dim3(Q_ / 128, BS_ / 128), 256, STG * STGB>>>(bv);
    k_scan_s  <<<B_, 1024>>>(out_w);
    k_pass1   <<<dim3(NC, B_), 256>>>();
    k_cscan   <<<B_ * (Q_ / 128), 128>>>();
    k_pass2   <<<dim3(NC, B_), 256>>>(out_u);
}